// round 1
// baseline (speedup 1.0000x reference)
#include <cuda_runtime.h>
#include <cuda_bf16.h>

#define IMG_H 1024
#define IMG_W 1024
#define N_PLANES 24   // B*C = 8*3
#define RES_SCALE 0.2f

__device__ __forceinline__ float med3f(float a, float b, float c) {
    // exact median of 3: max(min(a,b), min(max(a,b), c))
    return fmaxf(fminf(a, b), fminf(fmaxf(a, b), c));
}
__device__ __forceinline__ float min3f(float a, float b, float c) {
    return fminf(fminf(a, b), c);
}
__device__ __forceinline__ float max3f(float a, float b, float c) {
    return fmaxf(fmaxf(a, b), c);
}

__global__ __launch_bounds__(256, 8)
void MedianBlur_30966714204228_kernel(const float* __restrict__ x,
                                      float* __restrict__ out) {
    const int row   = blockIdx.x;       // 0..1023
    const int plane = blockIdx.y;       // 0..23
    const int c0    = threadIdx.x << 2; // 4 pixels per thread

    const float* p  = x + (size_t)plane * (IMG_H * IMG_W);
    const float* r0 = p + (size_t)row * IMG_W;
    const float* rm = r0 - IMG_W;
    const float* rp = r0 + IMG_W;
    const bool hasUp = (row > 0);
    const bool hasDn = (row < IMG_H - 1);

    const float4 z4 = make_float4(0.f, 0.f, 0.f, 0.f);
    float4 a0 = hasUp ? *(const float4*)(rm + c0) : z4;
    float4 a1 =         *(const float4*)(r0 + c0);
    float4 a2 = hasDn ? *(const float4*)(rp + c0) : z4;

    // halo columns c0-1 and c0+4 (zero-padded at image edges)
    float lu = 0.f, lc = 0.f, ld = 0.f;
    if (c0 > 0) {
        if (hasUp) lu = rm[c0 - 1];
        lc = r0[c0 - 1];
        if (hasDn) ld = rp[c0 - 1];
    }
    float ru = 0.f, rc = 0.f, rd = 0.f;
    if (c0 + 4 < IMG_W) {
        if (hasUp) ru = rm[c0 + 4];
        rc = r0[c0 + 4];
        if (hasDn) rd = rp[c0 + 4];
    }

    // 6 columns of the 3-row strip: indices c0-1 .. c0+4
    float ta[6] = { lu, a0.x, a0.y, a0.z, a0.w, ru };
    float tb[6] = { lc, a1.x, a1.y, a1.z, a1.w, rc };
    float tc[6] = { ld, a2.x, a2.y, a2.z, a2.w, rd };

    float lo[6], mi[6], hi[6];
#pragma unroll
    for (int j = 0; j < 6; j++) {
        lo[j] = min3f(ta[j], tb[j], tc[j]);
        hi[j] = max3f(ta[j], tb[j], tc[j]);
        mi[j] = med3f(ta[j], tb[j], tc[j]);
    }

    float4 o;
    float* op = &o.x;
#pragma unroll
    for (int k = 0; k < 4; k++) {
        float m = med3f(max3f(lo[k], lo[k + 1], lo[k + 2]),
                        med3f(mi[k], mi[k + 1], mi[k + 2]),
                        min3f(hi[k], hi[k + 1], hi[k + 2]));
        float xv = tb[k + 1];
        op[k] = xv + RES_SCALE * (m - xv);
    }

    *(float4*)(out + (size_t)plane * (IMG_H * IMG_W) + (size_t)row * IMG_W + c0) = o;
}

extern "C" void kernel_launch(void* const* d_in, const int* in_sizes, int n_in,
                              void* d_out, int out_size) {
    const float* x = (const float*)d_in[0];
    float* o = (float*)d_out;
    dim3 grid(IMG_H, N_PLANES);
    MedianBlur_30966714204228_kernel<<<grid, 256>>>(x, o);
}

// round 2
// speedup vs baseline: 1.0007x; 1.0007x over previous
#include <cuda_runtime.h>
#include <cuda_bf16.h>

#define IMG_H 1024
#define IMG_W 1024
#define N_PLANES 24   // B*C = 8*3
#define RES_SCALE 0.2f

__device__ __forceinline__ float med3f(float a, float b, float c) {
    // exact median of 3
    return fmaxf(fminf(a, b), fminf(fmaxf(a, b), c));
}

__global__ __launch_bounds__(256)
void MedianBlur_30966714204228_kernel(const float* __restrict__ x,
                                      float* __restrict__ out) {
    const int pr    = blockIdx.x;        // row pair 0..511
    const int plane = blockIdx.y;        // 0..23
    const int r     = pr << 1;           // top output row of the pair
    const int tid   = threadIdx.x;
    const int lane  = tid & 31;
    const int c0    = tid << 2;          // 4 pixels per thread per row

    const float* p    = x + (size_t)plane * (IMG_H * IMG_W);
    const float* rowB = p + (size_t)r * IMG_W;       // row r
    const float* rowC = rowB + IMG_W;                // row r+1
    const bool hasA = (r > 0);                       // row r-1 exists
    const bool hasD = (r + 2 < IMG_H);               // row r+2 exists

    const float4 z4 = make_float4(0.f, 0.f, 0.f, 0.f);
    float4 va = hasA ? *(const float4*)(rowB - IMG_W + c0) : z4;  // row r-1
    float4 vb =        *(const float4*)(rowB + c0);               // row r
    float4 vc =        *(const float4*)(rowC + c0);               // row r+1
    float4 vd = hasD ? *(const float4*)(rowC + IMG_W + c0) : z4;  // row r+2

    // ---- halo columns via register exchange (no L1 traffic) ----
    const unsigned fm = 0xffffffffu;
    float lA = __shfl_up_sync(fm, va.w, 1);
    float lB = __shfl_up_sync(fm, vb.w, 1);
    float lC = __shfl_up_sync(fm, vc.w, 1);
    float lD = __shfl_up_sync(fm, vd.w, 1);
    float rA = __shfl_down_sync(fm, va.x, 1);
    float rB = __shfl_down_sync(fm, vb.x, 1);
    float rC = __shfl_down_sync(fm, vc.x, 1);
    float rD = __shfl_down_sync(fm, vd.x, 1);
    if (lane == 0) {   // needs column c0-1 from previous warp (or zero pad)
        const bool in = (c0 > 0);
        lA = (in && hasA) ? rowB[c0 - 1 - IMG_W] : 0.f;
        lB = in ? rowB[c0 - 1] : 0.f;
        lC = in ? rowC[c0 - 1] : 0.f;
        lD = (in && hasD) ? rowC[c0 - 1 + IMG_W] : 0.f;
    }
    if (lane == 31) {  // needs column c0+4 from next warp (or zero pad)
        const bool in = (c0 + 4 < IMG_W);
        rA = (in && hasA) ? rowB[c0 + 4 - IMG_W] : 0.f;
        rB = in ? rowB[c0 + 4] : 0.f;
        rC = in ? rowC[c0 + 4] : 0.f;
        rD = (in && hasD) ? rowC[c0 + 4 + IMG_W] : 0.f;
    }

    // 6 columns (c0-1 .. c0+4) of the 4-row strip
    float A[6]  = { lA, va.x, va.y, va.z, va.w, rA };
    float Bv[6] = { lB, vb.x, vb.y, vb.z, vb.w, rB };
    float Cv[6] = { lC, vc.x, vc.y, vc.z, vc.w, rC };
    float D[6]  = { lD, vd.x, vd.y, vd.z, vd.w, rD };

    // Column sorts for both windows, sharing the (B,C) pair sort.
    float lo0[6], mi0[6], hi0[6], lo1[6], mi1[6], hi1[6];
#pragma unroll
    for (int j = 0; j < 6; j++) {
        const float s = fminf(Bv[j], Cv[j]);
        const float t = fmaxf(Bv[j], Cv[j]);
        lo0[j] = fminf(A[j], s);
        hi0[j] = fmaxf(A[j], t);
        mi0[j] = fmaxf(s, fminf(A[j], t));
        lo1[j] = fminf(D[j], s);
        hi1[j] = fmaxf(D[j], t);
        mi1[j] = fmaxf(s, fminf(D[j], t));
    }

    float4 o0, o1;
    float* o0p = &o0.x;
    float* o1p = &o1.x;
#pragma unroll
    for (int k = 0; k < 4; k++) {
        // window at row r
        float mx = fmaxf(fmaxf(lo0[k], lo0[k + 1]), lo0[k + 2]);
        float mn = fminf(fminf(hi0[k], hi0[k + 1]), hi0[k + 2]);
        float md = med3f(mi0[k], mi0[k + 1], mi0[k + 2]);
        float mm = med3f(mx, md, mn);
        float xv = Bv[k + 1];
        o0p[k] = xv + RES_SCALE * (mm - xv);

        // window at row r+1
        mx = fmaxf(fmaxf(lo1[k], lo1[k + 1]), lo1[k + 2]);
        mn = fminf(fminf(hi1[k], hi1[k + 1]), hi1[k + 2]);
        md = med3f(mi1[k], mi1[k + 1], mi1[k + 2]);
        mm = med3f(mx, md, mn);
        xv = Cv[k + 1];
        o1p[k] = xv + RES_SCALE * (mm - xv);
    }

    float* ob = out + (size_t)plane * (IMG_H * IMG_W) + (size_t)r * IMG_W + c0;
    *(float4*)ob = o0;
    *(float4*)(ob + IMG_W) = o1;
}

extern "C" void kernel_launch(void* const* d_in, const int* in_sizes, int n_in,
                              void* d_out, int out_size) {
    const float* x = (const float*)d_in[0];
    float* o = (float*)d_out;
    dim3 grid(IMG_H / 2, N_PLANES);
    MedianBlur_30966714204228_kernel<<<grid, 256>>>(x, o);
}

// round 3
// speedup vs baseline: 1.1490x; 1.1483x over previous
#include <cuda_runtime.h>
#include <cuda_bf16.h>

#define IMG_H 1024
#define IMG_W 1024
#define N_PLANES 24   // B*C = 8*3
#define RES_SCALE 0.2f

__device__ __forceinline__ float med3f(float a, float b, float c) {
    return fmaxf(fminf(a, b), fminf(fmaxf(a, b), c));
}

__global__ __launch_bounds__(128)
void MedianBlur_30966714204228_kernel(const float* __restrict__ x,
                                      float* __restrict__ out) {
    const int pr    = blockIdx.x;        // row pair 0..511
    const int plane = blockIdx.y;        // 0..23
    const int r     = pr << 1;           // top output row
    const int tid   = threadIdx.x;       // 0..127
    const int lane  = tid & 31;
    const int c0    = tid << 3;          // 8 pixels per thread per row

    const float* p    = x + (size_t)plane * (IMG_H * IMG_W);
    const float* rowB = p + (size_t)r * IMG_W;       // row r
    const float* rowC = rowB + IMG_W;                // row r+1
    const bool hasA = (r > 0);
    const bool hasD = (r + 2 < IMG_H);

    const float4 z4 = make_float4(0.f, 0.f, 0.f, 0.f);
    // 8 front-batched 128-bit loads (rows r-1..r+2, cols c0..c0+7)
    float4 a0 = hasA ? *(const float4*)(rowB - IMG_W + c0)     : z4;
    float4 a1 = hasA ? *(const float4*)(rowB - IMG_W + c0 + 4) : z4;
    float4 b0 =        *(const float4*)(rowB + c0);
    float4 b1 =        *(const float4*)(rowB + c0 + 4);
    float4 cc0 =       *(const float4*)(rowC + c0);
    float4 cc1 =       *(const float4*)(rowC + c0 + 4);
    float4 d0 = hasD ? *(const float4*)(rowC + IMG_W + c0)     : z4;
    float4 d1 = hasD ? *(const float4*)(rowC + IMG_W + c0 + 4) : z4;

    // ---- halo columns via register exchange ----
    const unsigned fm = 0xffffffffu;
    float lA = __shfl_up_sync(fm, a1.w, 1);
    float lB = __shfl_up_sync(fm, b1.w, 1);
    float lC = __shfl_up_sync(fm, cc1.w, 1);
    float lD = __shfl_up_sync(fm, d1.w, 1);
    float rA = __shfl_down_sync(fm, a0.x, 1);
    float rB = __shfl_down_sync(fm, b0.x, 1);
    float rC = __shfl_down_sync(fm, cc0.x, 1);
    float rD = __shfl_down_sync(fm, d0.x, 1);
    if (lane == 0) {          // col c0-1 comes from previous warp / zero pad
        const bool in = (c0 > 0);
        lA = (in && hasA) ? rowB[c0 - 1 - IMG_W] : 0.f;
        lB = in ? rowB[c0 - 1] : 0.f;
        lC = in ? rowC[c0 - 1] : 0.f;
        lD = (in && hasD) ? rowC[c0 - 1 + IMG_W] : 0.f;
    }
    if (lane == 31) {         // col c0+8 comes from next warp / zero pad
        const bool in = (c0 + 8 < IMG_W);
        rA = (in && hasA) ? rowB[c0 + 8 - IMG_W] : 0.f;
        rB = in ? rowB[c0 + 8] : 0.f;
        rC = in ? rowC[c0 + 8] : 0.f;
        rD = (in && hasD) ? rowC[c0 + 8 + IMG_W] : 0.f;
    }

    // 10 columns: index 0 = c0-1, 1..8 = c0..c0+7, 9 = c0+8
    float A[10] = { lA, a0.x, a0.y, a0.z, a0.w, a1.x, a1.y, a1.z, a1.w, rA };
    float B[10] = { lB, b0.x, b0.y, b0.z, b0.w, b1.x, b1.y, b1.z, b1.w, rB };
    float C[10] = { lC, cc0.x, cc0.y, cc0.z, cc0.w, cc1.x, cc1.y, cc1.z, cc1.w, rC };
    float D[10] = { lD, d0.x, d0.y, d0.z, d0.w, d1.x, d1.y, d1.z, d1.w, rD };

    // Column sorts for both row-windows, sharing the (B,C) pair sort.
    float lo[2][10], mi[2][10], hi[2][10];
#pragma unroll
    for (int j = 0; j < 10; j++) {
        const float s = fminf(B[j], C[j]);
        const float t = fmaxf(B[j], C[j]);
        lo[0][j] = fminf(A[j], s);
        hi[0][j] = fmaxf(A[j], t);
        mi[0][j] = fmaxf(s, fminf(A[j], t));
        lo[1][j] = fminf(D[j], s);
        hi[1][j] = fmaxf(D[j], t);
        mi[1][j] = fmaxf(s, fminf(D[j], t));
    }

    float res[2][8];
#pragma unroll
    for (int w = 0; w < 2; w++) {
        const float* xr = (w == 0) ? B : C;
#pragma unroll
        for (int pi = 0; pi < 4; pi++) {
            const int i = 2 * pi + 1;     // shared pair (i, i+1)
            const float pmx = fmaxf(lo[w][i], lo[w][i + 1]);
            const float pmn = fminf(hi[w][i], hi[w][i + 1]);
            const float psn = fminf(mi[w][i], mi[w][i + 1]);
            const float psx = fmaxf(mi[w][i], mi[w][i + 1]);

            // window k = i-1 (uses pair + element i-1)
            {
                const float M  = fmaxf(lo[w][i - 1], pmx);
                const float N  = fminf(hi[w][i - 1], pmn);
                const float md = fmaxf(psn, fminf(psx, mi[w][i - 1]));
                const float m  = med3f(M, md, N);
                const float xv = xr[i];                 // center col of window k=i-1 is i
                res[w][i - 1] = xv + RES_SCALE * (m - xv);
            }
            // window k = i (uses pair + element i+2)
            {
                const float M  = fmaxf(pmx, lo[w][i + 2]);
                const float N  = fminf(pmn, hi[w][i + 2]);
                const float md = fmaxf(psn, fminf(psx, mi[w][i + 2]));
                const float m  = med3f(M, md, N);
                const float xv = xr[i + 1];             // center col of window k=i is i+1
                res[w][i] = xv + RES_SCALE * (m - xv);
            }
        }
    }

    float* ob = out + (size_t)plane * (IMG_H * IMG_W) + (size_t)r * IMG_W + c0;
    *(float4*)(ob)            = make_float4(res[0][0], res[0][1], res[0][2], res[0][3]);
    *(float4*)(ob + 4)        = make_float4(res[0][4], res[0][5], res[0][6], res[0][7]);
    *(float4*)(ob + IMG_W)    = make_float4(res[1][0], res[1][1], res[1][2], res[1][3]);
    *(float4*)(ob + IMG_W+4)  = make_float4(res[1][4], res[1][5], res[1][6], res[1][7]);
}

extern "C" void kernel_launch(void* const* d_in, const int* in_sizes, int n_in,
                              void* d_out, int out_size) {
    const float* x = (const float*)d_in[0];
    float* o = (float*)d_out;
    dim3 grid(IMG_H / 2, N_PLANES);
    MedianBlur_30966714204228_kernel<<<grid, 128>>>(x, o);
}

// round 4
// speedup vs baseline: 1.2740x; 1.1087x over previous
#include <cuda_runtime.h>
#include <cuda_bf16.h>

#define IMG_H 1024
#define IMG_W 1024
#define N_PLANES 24   // B*C = 8*3
#define RES_SCALE 0.2f

__device__ __forceinline__ float med3f(float a, float b, float c) {
    return fmaxf(fminf(a, b), fminf(fmaxf(a, b), c));
}

__global__ __launch_bounds__(128)
void MedianBlur_30966714204228_kernel(const float* __restrict__ x,
                                      float* __restrict__ out) {
    const int pr    = blockIdx.x;        // row pair 0..511
    const int plane = blockIdx.y;        // 0..23
    const int r     = pr << 1;           // top output row
    const int tid   = threadIdx.x;       // 0..127
    const int lane  = tid & 31;
    const int c0    = tid << 3;          // 8 pixels per thread per row

    const float* p    = x + (size_t)plane * (IMG_H * IMG_W);
    const float* rowB = p + (size_t)r * IMG_W;       // row r
    const float* rowC = rowB + IMG_W;                // row r+1
    const bool hasA = (r > 0);
    const bool hasD = (r + 2 < IMG_H);

    const float4 z4 = make_float4(0.f, 0.f, 0.f, 0.f);
    // 8 front-batched 128-bit loads (rows r-1..r+2, cols c0..c0+7)
    float4 a0 = hasA ? *(const float4*)(rowB - IMG_W + c0)     : z4;
    float4 a1 = hasA ? *(const float4*)(rowB - IMG_W + c0 + 4) : z4;
    float4 b0 =        *(const float4*)(rowB + c0);
    float4 b1 =        *(const float4*)(rowB + c0 + 4);
    float4 cc0 =       *(const float4*)(rowC + c0);
    float4 cc1 =       *(const float4*)(rowC + c0 + 4);
    float4 d0 = hasD ? *(const float4*)(rowC + IMG_W + c0)     : z4;
    float4 d1 = hasD ? *(const float4*)(rowC + IMG_W + c0 + 4) : z4;

    // ---- predicated halo loads (no branches, only lanes 0/31 active) ----
    const bool pL = (lane == 0);
    const bool pR = (lane == 31);
    const bool inL = (c0 > 0);
    const bool inR = (c0 + 8 < IMG_W);
    // issued early; consumed last (columns j=0 / j=9)
    float hlA = (pL & inL & hasA) ? rowB[c0 - 1 - IMG_W] : 0.f;
    float hlB = (pL & inL)        ? rowB[c0 - 1]         : 0.f;
    float hlC = (pL & inL)        ? rowC[c0 - 1]         : 0.f;
    float hlD = (pL & inL & hasD) ? rowC[c0 - 1 + IMG_W] : 0.f;
    float hrA = (pR & inR & hasA) ? rowB[c0 + 8 - IMG_W] : 0.f;
    float hrB = (pR & inR)        ? rowB[c0 + 8]         : 0.f;
    float hrC = (pR & inR)        ? rowC[c0 + 8]         : 0.f;
    float hrD = (pR & inR & hasD) ? rowC[c0 + 8 + IMG_W] : 0.f;

    // ---- intra-warp halo via register exchange ----
    const unsigned fm = 0xffffffffu;
    float sA = __shfl_up_sync(fm, a1.w, 1);
    float sB = __shfl_up_sync(fm, b1.w, 1);
    float sC = __shfl_up_sync(fm, cc1.w, 1);
    float sD = __shfl_up_sync(fm, d1.w, 1);
    float tA = __shfl_down_sync(fm, a0.x, 1);
    float tB = __shfl_down_sync(fm, b0.x, 1);
    float tC = __shfl_down_sync(fm, cc0.x, 1);
    float tD = __shfl_down_sync(fm, d0.x, 1);

    float lA = pL ? hlA : sA;
    float lB = pL ? hlB : sB;
    float lC = pL ? hlC : sC;
    float lD = pL ? hlD : sD;
    float rA = pR ? hrA : tA;
    float rB = pR ? hrB : tB;
    float rC = pR ? hrC : tC;
    float rD = pR ? hrD : tD;

    // 10 columns: index 0 = c0-1, 1..8 = c0..c0+7, 9 = c0+8
    float A[10] = { lA, a0.x, a0.y, a0.z, a0.w, a1.x, a1.y, a1.z, a1.w, rA };
    float B[10] = { lB, b0.x, b0.y, b0.z, b0.w, b1.x, b1.y, b1.z, b1.w, rB };
    float C[10] = { lC, cc0.x, cc0.y, cc0.z, cc0.w, cc1.x, cc1.y, cc1.z, cc1.w, rC };
    float D[10] = { lD, d0.x, d0.y, d0.z, d0.w, d1.x, d1.y, d1.z, d1.w, rD };

    // Column sorts for both row-windows, sharing the (B,C) pair sort.
    float lo[2][10], mi[2][10], hi[2][10];
#pragma unroll
    for (int j = 0; j < 10; j++) {
        const float s = fminf(B[j], C[j]);
        const float t = fmaxf(B[j], C[j]);
        lo[0][j] = fminf(A[j], s);
        hi[0][j] = fmaxf(A[j], t);
        mi[0][j] = fmaxf(s, fminf(A[j], t));
        lo[1][j] = fminf(D[j], s);
        hi[1][j] = fmaxf(D[j], t);
        mi[1][j] = fmaxf(s, fminf(D[j], t));
    }

    float res[2][8];
#pragma unroll
    for (int w = 0; w < 2; w++) {
        const float* xr = (w == 0) ? B : C;
#pragma unroll
        for (int pi = 0; pi < 4; pi++) {
            const int i = 2 * pi + 1;     // shared pair (i, i+1)
            const float pmx = fmaxf(lo[w][i], lo[w][i + 1]);
            const float pmn = fminf(hi[w][i], hi[w][i + 1]);
            const float psn = fminf(mi[w][i], mi[w][i + 1]);
            const float psx = fmaxf(mi[w][i], mi[w][i + 1]);

            // window k = i-1 (pair + element i-1)
            {
                const float M  = fmaxf(lo[w][i - 1], pmx);
                const float N  = fminf(hi[w][i - 1], pmn);
                const float md = fmaxf(psn, fminf(psx, mi[w][i - 1]));
                const float m  = med3f(M, md, N);
                const float xv = xr[i];
                res[w][i - 1] = xv + RES_SCALE * (m - xv);
            }
            // window k = i (pair + element i+2)
            {
                const float M  = fmaxf(pmx, lo[w][i + 2]);
                const float N  = fminf(pmn, hi[w][i + 2]);
                const float md = fmaxf(psn, fminf(psx, mi[w][i + 2]));
                const float m  = med3f(M, md, N);
                const float xv = xr[i + 1];
                res[w][i] = xv + RES_SCALE * (m - xv);
            }
        }
    }

    float* ob = out + (size_t)plane * (IMG_H * IMG_W) + (size_t)r * IMG_W + c0;
    // streaming stores: output is write-once, keep L2 for the reused input rows
    __stcs((float4*)(ob),           make_float4(res[0][0], res[0][1], res[0][2], res[0][3]));
    __stcs((float4*)(ob + 4),       make_float4(res[0][4], res[0][5], res[0][6], res[0][7]));
    __stcs((float4*)(ob + IMG_W),   make_float4(res[1][0], res[1][1], res[1][2], res[1][3]));
    __stcs((float4*)(ob + IMG_W+4), make_float4(res[1][4], res[1][5], res[1][6], res[1][7]));
}

extern "C" void kernel_launch(void* const* d_in, const int* in_sizes, int n_in,
                              void* d_out, int out_size) {
    const float* x = (const float*)d_in[0];
    float* o = (float*)d_out;
    dim3 grid(IMG_H / 2, N_PLANES);
    MedianBlur_30966714204228_kernel<<<grid, 128>>>(x, o);
}